// round 4
// baseline (speedup 1.0000x reference)
#include <cuda_runtime.h>

#define Hh   512
#define Bb   32
#define Tt   2048
#define W3H  1536   // 3*H row stride of W_attn

// ---------------- device scratch (no allocations allowed) ----------------
__device__ float g_u[Bb * Hh];      // W1@hidden + b_attn, per (b,h)
__device__ float g_w3c[Hh];         // W3 @ W_cov
__device__ float g_scores[Bb * Tt]; // pre-softmax scores

// ---------------- packed f32x2 helpers ----------------
__device__ __forceinline__ unsigned long long pack_dup(float x) {
    unsigned int u = __float_as_uint(x);
    return ((unsigned long long)u << 32) | (unsigned long long)u;
}
__device__ __forceinline__ float2 unpack2(unsigned long long d) {
    float2 r;
    r.x = __uint_as_float((unsigned int)(d & 0xFFFFFFFFull));
    r.y = __uint_as_float((unsigned int)(d >> 32));
    return r;
}
#define FFMA2(d, a, b) asm("fma.rn.f32x2 %0, %1, %2, %0;" : "+l"(d) : "l"(a), "l"(b))

// ---------------- kernel 1: tiny precompute ----------------
// blocks 0..31: u[b,h] = b_attn[h] + sum_k W_attn[h, k] * hidden[b,k]
// block 32:     w3c[h] = sum_k W_attn[h, 2H+k] * W_cov[k]
__global__ __launch_bounds__(512) void precompute_kernel(
    const float* __restrict__ hidden,  // [1,B,H]
    const float* __restrict__ W_attn,  // [H, 3H]
    const float* __restrict__ b_attn,  // [H]
    const float* __restrict__ W_cov)   // [H,1]
{
    __shared__ float sh[Hh];
    const int tx = threadIdx.x;        // 0..511 == h
    const int blk = blockIdx.x;

    if (blk < Bb) {
        sh[tx] = hidden[blk * Hh + tx];
        __syncthreads();
        const float4* wr = (const float4*)(W_attn + (size_t)tx * W3H);
        const float4* s4 = (const float4*)sh;
        float a0 = 0.f, a1 = 0.f, a2 = 0.f, a3 = 0.f;
        #pragma unroll 8
        for (int k = 0; k < Hh / 4; k++) {
            float4 w = wr[k], s = s4[k];
            a0 += w.x * s.x; a1 += w.y * s.y; a2 += w.z * s.z; a3 += w.w * s.w;
        }
        g_u[blk * Hh + tx] = (a0 + a1) + (a2 + a3) + b_attn[tx];
    } else {
        sh[tx] = W_cov[tx];
        __syncthreads();
        const float4* wr = (const float4*)(W_attn + (size_t)tx * W3H + 2 * Hh);
        const float4* s4 = (const float4*)sh;
        float a0 = 0.f, a1 = 0.f, a2 = 0.f, a3 = 0.f;
        #pragma unroll 8
        for (int k = 0; k < Hh / 4; k++) {
            float4 w = wr[k], s = s4[k];
            a0 += w.x * s.x; a1 += w.y * s.y; a2 += w.z * s.z; a3 += w.w * s.w;
        }
        g_w3c[tx] = (a0 + a1) + (a2 + a3);
    }
}

// ---------------- kernel 2: fused GEMM(W2@enc) + relu + v-dot ----------------
// Block = (t-tile of 128, batch b). Per-thread microtile 8(t) x 4(h) using
// packed f32x2 FFMA. h-tiles of 64 looped inside the block; after each
// h-tile's full-K accumulation: energy -> relu -> v-weighted partial score.
#define TILE_T 128
#define TILE_H 64
#define KB     16

__global__ __launch_bounds__(256) void energy_scores_kernel(
    const float* __restrict__ enc,       // [T,B,H]
    const float* __restrict__ coverage,  // [B,T]
    const float* __restrict__ W_attn,    // [H,3H]; W2 at col offset H
    const float* __restrict__ v)         // [H]
{
    __shared__ float enc_s[KB][TILE_T];                   // 8 KB, [k][t]
    __shared__ unsigned long long w2d[KB][TILE_H];        // 8 KB, [k][h] dup'd pairs
    __shared__ float sred[16][TILE_T];                    // 8 KB, score reduce

    const int tx = threadIdx.x;           // 0..255
    const int b  = blockIdx.y;
    const int t0 = blockIdx.x * TILE_T;

    // compute-phase coordinates
    const int t_base = (tx & 15) * 8;     // 8 consecutive t's
    const int h_base = (tx >> 4) * 4;     // 4 consecutive h's
    // load-phase coordinates
    const int t_load   = tx & 127;        // enc: one t, 8 k's
    const int k_load_e = (tx >> 7) * 8;
    const int h_load   = tx & 63;         // W2: one h, 4 k's
    const int k_load_w = (tx >> 6) * 4;

    float covv[8];
    #pragma unroll
    for (int i = 0; i < 8; i++) covv[i] = coverage[b * Tt + t0 + t_base + i];

    const float* encp = enc + (size_t)(t0 + t_load) * (Bb * Hh) + (size_t)b * Hh;

    float sc[8];
    #pragma unroll
    for (int i = 0; i < 8; i++) sc[i] = 0.f;

    for (int ht = 0; ht < Hh; ht += TILE_H) {
        unsigned long long acc[4][4];
        #pragma unroll
        for (int p = 0; p < 4; p++)
            #pragma unroll
            for (int j = 0; j < 4; j++) acc[p][j] = 0ull;

        const float* wp = W_attn + (size_t)(ht + h_load) * W3H + Hh + k_load_w;

        for (int k0 = 0; k0 < Hh; k0 += KB) {
            float4 e0 = *(const float4*)(encp + k0 + k_load_e);
            float4 e1 = *(const float4*)(encp + k0 + k_load_e + 4);
            float4 w  = *(const float4*)(wp + k0);

            enc_s[k_load_e + 0][t_load] = e0.x;
            enc_s[k_load_e + 1][t_load] = e0.y;
            enc_s[k_load_e + 2][t_load] = e0.z;
            enc_s[k_load_e + 3][t_load] = e0.w;
            enc_s[k_load_e + 4][t_load] = e1.x;
            enc_s[k_load_e + 5][t_load] = e1.y;
            enc_s[k_load_e + 6][t_load] = e1.z;
            enc_s[k_load_e + 7][t_load] = e1.w;

            w2d[k_load_w + 0][h_load] = pack_dup(w.x);
            w2d[k_load_w + 1][h_load] = pack_dup(w.y);
            w2d[k_load_w + 2][h_load] = pack_dup(w.z);
            w2d[k_load_w + 3][h_load] = pack_dup(w.w);
            __syncthreads();

            #pragma unroll
            for (int k = 0; k < KB; k++) {
                const ulonglong2 a01 = *(const ulonglong2*)&enc_s[k][t_base];
                const ulonglong2 a23 = *(const ulonglong2*)&enc_s[k][t_base + 4];
                const ulonglong2 b01 = *(const ulonglong2*)&w2d[k][h_base];
                const ulonglong2 b23 = *(const ulonglong2*)&w2d[k][h_base + 2];
                FFMA2(acc[0][0], a01.x, b01.x);
                FFMA2(acc[0][1], a01.x, b01.y);
                FFMA2(acc[0][2], a01.x, b23.x);
                FFMA2(acc[0][3], a01.x, b23.y);
                FFMA2(acc[1][0], a01.y, b01.x);
                FFMA2(acc[1][1], a01.y, b01.y);
                FFMA2(acc[1][2], a01.y, b23.x);
                FFMA2(acc[1][3], a01.y, b23.y);
                FFMA2(acc[2][0], a23.x, b01.x);
                FFMA2(acc[2][1], a23.x, b01.y);
                FFMA2(acc[2][2], a23.x, b23.x);
                FFMA2(acc[2][3], a23.x, b23.y);
                FFMA2(acc[3][0], a23.y, b01.x);
                FFMA2(acc[3][1], a23.y, b01.y);
                FFMA2(acc[3][2], a23.y, b23.x);
                FFMA2(acc[3][3], a23.y, b23.y);
            }
            __syncthreads();
        }

        // epilogue for this h-tile: energy + relu + v-dot (register-only smem-wise)
        #pragma unroll
        for (int j = 0; j < 4; j++) {
            const int h = ht + h_base + j;
            const float uu = g_u[b * Hh + h];
            const float w3 = g_w3c[h];
            const float vv = __ldg(v + h);
            #pragma unroll
            for (int p = 0; p < 4; p++) {
                float2 e = unpack2(acc[p][j]);
                float ea = e.x + uu + covv[2 * p]     * w3;
                float eb = e.y + uu + covv[2 * p + 1] * w3;
                sc[2 * p]     += vv * fmaxf(ea, 0.f);
                sc[2 * p + 1] += vv * fmaxf(eb, 0.f);
            }
        }
    }

    // reduce 16 h-groups -> scores[t]
    const int g = tx >> 4;
    #pragma unroll
    for (int i = 0; i < 8; i++) sred[g][t_base + i] = sc[i];
    __syncthreads();
    if (tx < TILE_T) {
        float s = 0.f;
        #pragma unroll
        for (int gg = 0; gg < 16; gg++) s += sred[gg][tx];
        g_scores[b * Tt + t0 + tx] = s;
    }
}

// ---------------- kernel 3: softmax over T + coverage update ----------------
__global__ __launch_bounds__(256) void softmax_kernel(
    const float* __restrict__ coverage, float* __restrict__ out, int write_cov)
{
    __shared__ float red[256];
    const int b = blockIdx.x, tx = threadIdx.x;
    const float* s = g_scores + b * Tt;

    float m = -3.0e38f;
    for (int t = tx; t < Tt; t += 256) m = fmaxf(m, s[t]);
    red[tx] = m; __syncthreads();
    for (int o = 128; o > 0; o >>= 1) {
        if (tx < o) red[tx] = fmaxf(red[tx], red[tx + o]);
        __syncthreads();
    }
    m = red[0]; __syncthreads();

    float sum = 0.f;
    for (int t = tx; t < Tt; t += 256) sum += expf(s[t] - m);
    red[tx] = sum; __syncthreads();
    for (int o = 128; o > 0; o >>= 1) {
        if (tx < o) red[tx] += red[tx + o];
        __syncthreads();
    }
    const float inv = 1.f / red[0];

    for (int t = tx; t < Tt; t += 256) {
        float w = expf(s[t] - m) * inv;
        out[b * Tt + t] = w;                                        // attn_weights [B,1,T]
        if (write_cov) out[Bb * Tt + b * Tt + t] = coverage[b * Tt + t] + w;  // coverage_new
    }
}

// ---------------- launch ----------------
extern "C" void kernel_launch(void* const* d_in, const int* in_sizes, int n_in,
                              void* d_out, int out_size) {
    const float* hidden   = (const float*)d_in[0];  // [1,B,H]
    const float* enc      = (const float*)d_in[1];  // [T,B,H]
    const float* coverage = (const float*)d_in[2];  // [B,T]
    const float* W_attn   = (const float*)d_in[3];  // [H,3H]
    const float* b_attn   = (const float*)d_in[4];  // [H]
    const float* v        = (const float*)d_in[5];  // [H]
    const float* W_cov    = (const float*)d_in[6];  // [H,1]
    float* out = (float*)d_out;

    precompute_kernel<<<Bb + 1, 512>>>(hidden, W_attn, b_attn, W_cov);

    dim3 grid(Tt / TILE_T, Bb);                      // 16 x 32 = 512 blocks
    energy_scores_kernel<<<grid, 256>>>(enc, coverage, W_attn, v);

    const int write_cov = (out_size >= 2 * Bb * Tt) ? 1 : 0;
    softmax_kernel<<<Bb, 256>>>(coverage, out, write_cov);
}

// round 9
// speedup vs baseline: 14.9558x; 14.9558x over previous
#include <cuda_runtime.h>
#include <cuda_bf16.h>

#define Hh   512
#define Bb   32
#define Tt   2048
#define W3H  1536

// ---------------- device scratch ----------------
__device__ float g_u[Bb * Hh];           // W1@hidden + b_attn
__device__ float g_w3c[Hh];              // W3 @ W_cov
__device__ float g_scores[Bb * Tt];      // pre-softmax scores
__device__ __nv_bfloat16 g_w2b[Hh * Hh]; // W2 in bf16, [h][k]

// ---------------- PTX helpers (baseline ISA only: sm_80-class) ----------------
static __device__ __forceinline__ unsigned smem_u32(const void* p) {
    unsigned a;
    asm("{ .reg .u64 t; cvta.to.shared.u64 t, %1; cvt.u32.u64 %0, t; }" : "=r"(a) : "l"(p));
    return a;
}

#define LDSM_X4(r, a) \
    asm volatile("ldmatrix.sync.aligned.m8n8.x4.shared.b16 {%0,%1,%2,%3}, [%4];" \
        : "=r"((r)[0]), "=r"((r)[1]), "=r"((r)[2]), "=r"((r)[3]) : "r"(a))

#define MMA_BF16(c, a, b0, b1) \
    asm volatile("mma.sync.aligned.m16n8k16.row.col.f32.bf16.bf16.f32 " \
        "{%0,%1,%2,%3}, {%4,%5,%6,%7}, {%8,%9}, {%0,%1,%2,%3};" \
        : "+f"((c)[0]), "+f"((c)[1]), "+f"((c)[2]), "+f"((c)[3]) \
        : "r"((a)[0]), "r"((a)[1]), "r"((a)[2]), "r"((a)[3]), "r"(b0), "r"(b1))

#define CP_ASYNC16(dst, src) \
    asm volatile("cp.async.cg.shared.global [%0], [%1], 16;" :: "r"(dst), "l"(src) : "memory")
#define CP_COMMIT() asm volatile("cp.async.commit_group;" ::: "memory")
#define CP_WAIT3()  asm volatile("cp.async.wait_group 3;" ::: "memory")

// swizzle: 128B rows, XOR bits[4:6] with row bits (row&7)
static __device__ __forceinline__ unsigned swz(unsigned o) { return o ^ ((o >> 3) & 0x70u); }

// ---------------- kernel 0: W2 fp32 -> bf16 ----------------
__global__ __launch_bounds__(256) void w2_convert_kernel(const float* __restrict__ W_attn) {
    int i = (blockIdx.x * 256 + threadIdx.x) * 4;
    int h = i >> 9, k = i & 511;
    float4 w = *(const float4*)(W_attn + (size_t)h * W3H + Hh + k);
    __nv_bfloat162 p0 = __floats2bfloat162_rn(w.x, w.y);
    __nv_bfloat162 p1 = __floats2bfloat162_rn(w.z, w.w);
    uint2 uu;
    uu.x = *reinterpret_cast<unsigned*>(&p0);
    uu.y = *reinterpret_cast<unsigned*>(&p1);
    *(uint2*)(g_w2b + i) = uu;
}

// ---------------- kernel 1: u[b,h], w3c[h] (fp32 exact) ----------------
__global__ __launch_bounds__(512) void precompute_kernel(
    const float* __restrict__ hidden, const float* __restrict__ W_attn,
    const float* __restrict__ b_attn, const float* __restrict__ W_cov)
{
    __shared__ float sh[Hh];
    __shared__ float red[64][9];
    const int tx = threadIdx.x;
    const int bx = blockIdx.x;
    const int hy = blockIdx.y;
    sh[tx] = (bx < Bb) ? hidden[bx * Hh + tx] : W_cov[tx];
    __syncthreads();
    const int hl = tx >> 3, ks = tx & 7;
    const int h = hy * 64 + hl;
    const float* wr = W_attn + (size_t)h * W3H + (bx < Bb ? 0 : 2 * Hh) + ks * 64;
    const float4* w4 = (const float4*)wr;
    const float4* s4 = (const float4*)(sh + ks * 64);
    float a0 = 0.f, a1 = 0.f, a2 = 0.f, a3 = 0.f;
    #pragma unroll
    for (int j = 0; j < 16; j++) {
        float4 w = w4[j], s = s4[j];
        a0 += w.x * s.x; a1 += w.y * s.y; a2 += w.z * s.z; a3 += w.w * s.w;
    }
    red[hl][ks] = (a0 + a1) + (a2 + a3);
    __syncthreads();
    if (tx < 64) {
        float s = 0.f;
        #pragma unroll
        for (int q = 0; q < 8; q++) s += red[tx][q];
        int hh = hy * 64 + tx;
        if (bx < Bb) g_u[bx * Hh + hh] = s + b_attn[hh];
        else         g_w3c[hh] = s;
    }
}

// ---------------- kernel 2: warp-MMA GEMM + fused epilogue -> scores ----------------
// SMEM layout (bytes from dynamic base):
#define OFF_SU    0
#define OFF_SW3   2048
#define OFF_SV    4096
#define OFF_SRED  6144                 // 256 floats
#define OFF_A     8192                 // 8 chunks x [128 rows x 128 B] = 131072
#define OFF_B     (8192 + 131072)      // 4 bufs x [64 rows x 128 B] = 32768
#define GEMM_SMEM (OFF_B + 32768)      // 172032

__global__ __launch_bounds__(256, 1)
void gemm_scores_kernel(const float* __restrict__ enc,
                        const float* __restrict__ coverage,
                        const float* __restrict__ v)
{
    extern __shared__ char smem[];
    const unsigned sb = smem_u32(smem);
    const int tx = threadIdx.x;
    const int wid = tx >> 5, l = tx & 31;
    const int mw = wid & 3, nw = wid >> 2;      // 4 m-subtiles x 2 n-subtiles
    const int b = blockIdx.y;
    const int t0 = blockIdx.x * 128;

    float* su  = (float*)(smem + OFF_SU);
    float* sw3 = (float*)(smem + OFF_SW3);
    float* sv  = (float*)(smem + OFF_SV);

    // ---- B chunk loader via cp.async: chunk i -> (ht=i>>3, kc=i&7), buf i&3 ----
    auto load_b = [&](int i) {
        const int ht = i >> 3, kc = i & 7;
        const unsigned bufo = sb + OFF_B + (unsigned)(i & 3) * 8192;
        #pragma unroll
        for (int j = 0; j < 2; j++) {
            const int idx = tx + j * 256;
            const int row = idx >> 3, seg = idx & 7;
            const __nv_bfloat16* src = g_w2b + (size_t)(ht * 64 + row) * Hh + kc * 64 + seg * 8;
            CP_ASYNC16(bufo + swz((unsigned)(row * 128 + seg * 16)), src);
        }
    };

    load_b(0); CP_COMMIT();
    load_b(1); CP_COMMIT();
    load_b(2); CP_COMMIT();

    // ---- epilogue vectors ----
    for (int i = tx; i < Hh; i += 256) {
        su[i] = g_u[b * Hh + i]; sw3[i] = g_w3c[i]; sv[i] = v[i];
    }

    // ---- A tile: enc rows t0..t0+127 of batch b, fp32 -> bf16 swizzled smem ----
    {
        const int rs = tx >> 4, kg = tx & 15;
        #pragma unroll
        for (int rr = 0; rr < 8; rr++) {
            const int r = rr * 16 + rs;
            const float* rowp = enc + ((size_t)(t0 + r) * Bb + b) * Hh;
            #pragma unroll
            for (int kk = 0; kk < 8; kk++) {
                const int k0 = kk * 64 + kg * 4;
                float4 e = *(const float4*)(rowp + k0);
                __nv_bfloat162 p0 = __floats2bfloat162_rn(e.x, e.y);
                __nv_bfloat162 p1 = __floats2bfloat162_rn(e.z, e.w);
                uint2 uu;
                uu.x = *reinterpret_cast<unsigned*>(&p0);
                uu.y = *reinterpret_cast<unsigned*>(&p1);
                *(uint2*)(smem + OFF_A + kk * 16384 +
                          swz((unsigned)(r * 128 + (k0 & 63) * 2))) = uu;
            }
        }
    }

    // ---- per-lane ldmatrix address precompute ----
    // A (row-major m16k16 frags): tiles t: rows +((t&1)*8), cols +((t>>1)*8)
    unsigned aBase[2], aXor[2];
    {
        const int rA = mw * 32 + ((l >> 3) & 1) * 8 + (l & 7);
        #pragma unroll
        for (int mi = 0; mi < 2; mi++) {
            const int row = rA + mi * 16;
            aBase[mi] = sb + OFF_A + (unsigned)(row * 128);
            aXor[mi]  = (unsigned)((row & 7) << 4);
        }
    }
    const int cbA = ((l >> 4) & 1) * 8;
    // B ([n][k] rows, no trans): tiles t: rows +((t>>1)*8), cols +((t&1)*8)
    unsigned bBase[2], bXor[2];
    {
        const int rB = nw * 32 + ((l >> 4) & 1) * 8 + (l & 7);
        #pragma unroll
        for (int nj = 0; nj < 2; nj++) {
            const int row = rB + nj * 16;
            bBase[nj] = sb + OFF_B + (unsigned)(row * 128);
            bXor[nj]  = (unsigned)((row & 7) << 4);
        }
    }
    const int cbB = ((l >> 3) & 1) * 8;

    // coverage for this thread's 4 rows: mi*16 + (l>>2) + half*8
    float cov[4];
    #pragma unroll
    for (int mi = 0; mi < 2; mi++)
        #pragma unroll
        for (int half = 0; half < 2; half++)
            cov[mi * 2 + half] =
                coverage[b * Tt + t0 + mw * 32 + mi * 16 + (l >> 2) + half * 8];

    float acc[2][4][4];
    float sc[4] = {0.f, 0.f, 0.f, 0.f};
    const int c0 = (l & 3) * 2;

    // ---- main pipeline: 64 chunks, 3-deep cp.async ----
    for (int i = 0; i < 64; i++) {
        if (i + 3 < 64) load_b(i + 3);
        CP_COMMIT();                       // empty groups near the end keep count stable
        CP_WAIT3();
        __syncthreads();

        const int kc = i & 7, ht = i >> 3;
        if (kc == 0) {
            #pragma unroll
            for (int mi = 0; mi < 2; mi++)
                #pragma unroll
                for (int ni = 0; ni < 4; ni++)
                    #pragma unroll
                    for (int q = 0; q < 4; q++) acc[mi][ni][q] = 0.f;
        }

        const unsigned aK = (unsigned)kc * 16384;
        const unsigned bB = (unsigned)(i & 3) * 8192;
        #pragma unroll
        for (int s = 0; s < 4; s++) {
            const int kk = s * 16;
            unsigned av[2][4], bv[2][4];
            #pragma unroll
            for (int mi = 0; mi < 2; mi++)
                LDSM_X4(av[mi], aBase[mi] + aK + ((unsigned)((kk + cbA) * 2) ^ aXor[mi]));
            #pragma unroll
            for (int nj = 0; nj < 2; nj++)
                LDSM_X4(bv[nj], bBase[nj] + bB + ((unsigned)((kk + cbB) * 2) ^ bXor[nj]));
            #pragma unroll
            for (int mi = 0; mi < 2; mi++) {
                MMA_BF16(acc[mi][0], av[mi], bv[0][0], bv[0][1]);
                MMA_BF16(acc[mi][1], av[mi], bv[0][2], bv[0][3]);
                MMA_BF16(acc[mi][2], av[mi], bv[1][0], bv[1][1]);
                MMA_BF16(acc[mi][3], av[mi], bv[1][2], bv[1][3]);
            }
        }

        if (kc == 7) {
            // epilogue for h-tile ht: energy + u + cov*w3c -> relu -> dot v
            #pragma unroll
            for (int ni = 0; ni < 4; ni++) {
                const int h = ht * 64 + nw * 32 + ni * 8 + c0;
                const float2 u2 = *(const float2*)&su[h];
                const float2 w2 = *(const float2*)&sw3[h];
                const float2 v2 = *(const float2*)&sv[h];
                #pragma unroll
                for (int mi = 0; mi < 2; mi++) {
                    float e0 = acc[mi][ni][0] + u2.x + cov[mi * 2] * w2.x;
                    float e1 = acc[mi][ni][1] + u2.y + cov[mi * 2] * w2.y;
                    sc[mi * 2] += v2.x * fmaxf(e0, 0.f) + v2.y * fmaxf(e1, 0.f);
                    float e2 = acc[mi][ni][2] + u2.x + cov[mi * 2 + 1] * w2.x;
                    float e3 = acc[mi][ni][3] + u2.y + cov[mi * 2 + 1] * w2.y;
                    sc[mi * 2 + 1] += v2.x * fmaxf(e2, 0.f) + v2.y * fmaxf(e3, 0.f);
                }
            }
        }
        __syncthreads();
    }

    // ---- reduce: sum over the 4 lanes sharing a row, then over the 2 n-warps ----
    #pragma unroll
    for (int q = 1; q < 4; q <<= 1)
        #pragma unroll
        for (int j = 0; j < 4; j++)
            sc[j] += __shfl_xor_sync(0xFFFFFFFFu, sc[j], q);

    float* sred = (float*)(smem + OFF_SRED);
    if ((l & 3) == 0) {
        #pragma unroll
        for (int mi = 0; mi < 2; mi++)
            #pragma unroll
            for (int half = 0; half < 2; half++)
                sred[nw * 128 + mw * 32 + mi * 16 + (l >> 2) + half * 8] = sc[mi * 2 + half];
    }
    __syncthreads();
    if (tx < 128) g_scores[b * Tt + t0 + tx] = sred[tx] + sred[128 + tx];
}

// ---------------- kernel 3: softmax over T + coverage update ----------------
__global__ __launch_bounds__(256) void softmax_kernel(
    const float* __restrict__ coverage, float* __restrict__ out, int write_cov)
{
    __shared__ float red[256];
    const int b = blockIdx.x, tx = threadIdx.x;
    const float* s = g_scores + b * Tt;

    float m = -3.0e38f;
    for (int t = tx; t < Tt; t += 256) m = fmaxf(m, s[t]);
    red[tx] = m; __syncthreads();
    for (int o = 128; o > 0; o >>= 1) {
        if (tx < o) red[tx] = fmaxf(red[tx], red[tx + o]);
        __syncthreads();
    }
    m = red[0]; __syncthreads();

    float sum = 0.f;
    for (int t = tx; t < Tt; t += 256) sum += expf(s[t] - m);
    red[tx] = sum; __syncthreads();
    for (int o = 128; o > 0; o >>= 1) {
        if (tx < o) red[tx] += red[tx + o];
        __syncthreads();
    }
    const float inv = 1.f / red[0];

    for (int t = tx; t < Tt; t += 256) {
        float w = expf(s[t] - m) * inv;
        out[b * Tt + t] = w;
        if (write_cov) out[Bb * Tt + b * Tt + t] = coverage[b * Tt + t] + w;
    }
}

// ---------------- launch ----------------
extern "C" void kernel_launch(void* const* d_in, const int* in_sizes, int n_in,
                              void* d_out, int out_size) {
    const float* hidden   = (const float*)d_in[0];
    const float* enc      = (const float*)d_in[1];
    const float* coverage = (const float*)d_in[2];
    const float* W_attn   = (const float*)d_in[3];
    const float* b_attn   = (const float*)d_in[4];
    const float* v        = (const float*)d_in[5];
    const float* W_cov    = (const float*)d_in[6];
    float* out = (float*)d_out;

    cudaFuncSetAttribute(gemm_scores_kernel,
                         cudaFuncAttributeMaxDynamicSharedMemorySize, GEMM_SMEM);

    w2_convert_kernel<<<256, 256>>>(W_attn);
    precompute_kernel<<<dim3(Bb + 1, 8), 512>>>(hidden, W_attn, b_attn, W_cov);
    gemm_scores_kernel<<<dim3(Tt / 128, Bb), 256, GEMM_SMEM>>>(enc, coverage, v);

    const int write_cov = (out_size >= 2 * Bb * Tt) ? 1 : 0;
    softmax_kernel<<<Bb, 256>>>(coverage, out, write_cov);
}

// round 10
// speedup vs baseline: 16.6222x; 1.1114x over previous
#include <cuda_runtime.h>
#include <cuda_fp16.h>

#define Hh   512
#define Bb   32
#define Tt   2048
#define W3H  1536

// ---------------- device scratch ----------------
__device__ float g_u[Bb * Hh];      // W1@hidden + b_attn
__device__ float g_w3c[Hh];         // W3 @ W_cov
__device__ float g_scores[Bb * Tt]; // pre-softmax scores
__device__ __half g_w2h[Hh * Hh];   // W2 in fp16, [h][k]

// ---------------- PTX helpers (baseline ISA only) ----------------
static __device__ __forceinline__ unsigned smem_u32(const void* p) {
    unsigned a;
    asm("{ .reg .u64 t; cvta.to.shared.u64 t, %1; cvt.u32.u64 %0, t; }" : "=r"(a) : "l"(p));
    return a;
}

#define LDSM_X4(r, a) \
    asm volatile("ldmatrix.sync.aligned.m8n8.x4.shared.b16 {%0,%1,%2,%3}, [%4];" \
        : "=r"((r)[0]), "=r"((r)[1]), "=r"((r)[2]), "=r"((r)[3]) : "r"(a))

#define MMA_F16(c, a, b0, b1) \
    asm volatile("mma.sync.aligned.m16n8k16.row.col.f32.f16.f16.f32 " \
        "{%0,%1,%2,%3}, {%4,%5,%6,%7}, {%8,%9}, {%0,%1,%2,%3};" \
        : "+f"((c)[0]), "+f"((c)[1]), "+f"((c)[2]), "+f"((c)[3]) \
        : "r"((a)[0]), "r"((a)[1]), "r"((a)[2]), "r"((a)[3]), "r"(b0), "r"(b1))

#define CP_ASYNC16(dst, src) \
    asm volatile("cp.async.cg.shared.global [%0], [%1], 16;" :: "r"(dst), "l"(src) : "memory")
#define CP_COMMIT() asm volatile("cp.async.commit_group;" ::: "memory")
#define CP_WAIT2()  asm volatile("cp.async.wait_group 2;" ::: "memory")

// swizzle: 128B rows, XOR bits[4:6] with row bits (row&7)
static __device__ __forceinline__ unsigned swz(unsigned o) { return o ^ ((o >> 3) & 0x70u); }

// ---------------- kernel 0: W2 fp32 -> fp16 ----------------
__global__ __launch_bounds__(256) void w2_convert_kernel(const float* __restrict__ W_attn) {
    int i = (blockIdx.x * 256 + threadIdx.x) * 4;
    int h = i >> 9, k = i & 511;
    float4 w = *(const float4*)(W_attn + (size_t)h * W3H + Hh + k);
    __half2 p0 = __floats2half2_rn(w.x, w.y);
    __half2 p1 = __floats2half2_rn(w.z, w.w);
    uint2 uu;
    uu.x = *reinterpret_cast<unsigned*>(&p0);
    uu.y = *reinterpret_cast<unsigned*>(&p1);
    *(uint2*)(g_w2h + i) = uu;
}

// ---------------- kernel 1: u[b,h], w3c[h] (fp32 exact) ----------------
__global__ __launch_bounds__(512) void precompute_kernel(
    const float* __restrict__ hidden, const float* __restrict__ W_attn,
    const float* __restrict__ b_attn, const float* __restrict__ W_cov)
{
    __shared__ float sh[Hh];
    __shared__ float red[64][9];
    const int tx = threadIdx.x;
    const int bx = blockIdx.x;
    const int hy = blockIdx.y;
    sh[tx] = (bx < Bb) ? hidden[bx * Hh + tx] : W_cov[tx];
    __syncthreads();
    const int hl = tx >> 3, ks = tx & 7;
    const int h = hy * 64 + hl;
    const float* wr = W_attn + (size_t)h * W3H + (bx < Bb ? 0 : 2 * Hh) + ks * 64;
    const float4* w4 = (const float4*)wr;
    const float4* s4 = (const float4*)(sh + ks * 64);
    float a0 = 0.f, a1 = 0.f, a2 = 0.f, a3 = 0.f;
    #pragma unroll
    for (int j = 0; j < 16; j++) {
        float4 w = w4[j], s = s4[j];
        a0 += w.x * s.x; a1 += w.y * s.y; a2 += w.z * s.z; a3 += w.w * s.w;
    }
    red[hl][ks] = (a0 + a1) + (a2 + a3);
    __syncthreads();
    if (tx < 64) {
        float s = 0.f;
        #pragma unroll
        for (int q = 0; q < 8; q++) s += red[tx][q];
        int hh = hy * 64 + tx;
        if (bx < Bb) g_u[bx * Hh + hh] = s + b_attn[hh];
        else         g_w3c[hh] = s;
    }
}

// ---------------- kernel 2: warp-MMA GEMM + fused epilogue -> scores ----------------
// SMEM layout (bytes from dynamic base):
#define OFF_SU    0
#define OFF_SW3   2048
#define OFF_SV    4096
#define OFF_SRED  6144                 // 256 floats
#define OFF_A     8192                 // 8 sections x [128 rows x 128 B] = 131072
#define OFF_B     (8192 + 131072)      // 4 bufs x [2 halves x 64 rows x 128 B] = 65536
#define GEMM_SMEM (OFF_B + 65536)      // 204800

__global__ __launch_bounds__(256, 1)
void gemm_scores_kernel(const float* __restrict__ enc,
                        const float* __restrict__ coverage,
                        const float* __restrict__ v)
{
    extern __shared__ char smem[];
    const unsigned sb = smem_u32(smem);
    const int tx = threadIdx.x;
    const int wid = tx >> 5, l = tx & 31;
    const int mw = wid & 3, nw = wid >> 2;      // 4 m-subtiles x 2 n-subtiles
    const int b = blockIdx.y;
    const int t0 = blockIdx.x * 128;

    float* su  = (float*)(smem + OFF_SU);
    float* sw3 = (float*)(smem + OFF_SW3);
    float* sv  = (float*)(smem + OFF_SV);

    // ---- B chunk loader via cp.async: chunk i -> (ht=i>>2, kc2=i&3), buf i&3 ----
    // chunk = 64 h-rows x 128 k, stored as two 64x128B halves (half = k/64 within chunk)
    auto load_b = [&](int i) {
        const int ht = i >> 2, kc2 = i & 3;
        const unsigned bufo = sb + OFF_B + (unsigned)(i & 3) * 16384;
        #pragma unroll
        for (int j = 0; j < 4; j++) {
            const int idx = tx + j * 256;              // 0..1023
            const int row = idx >> 4;                  // 0..63
            const int half = (idx >> 3) & 1;
            const int seg = idx & 7;
            const __half* src = g_w2h + (size_t)(ht * 64 + row) * Hh
                              + kc2 * 128 + half * 64 + seg * 8;
            CP_ASYNC16(bufo + (unsigned)half * 8192 + swz((unsigned)(row * 128 + seg * 16)), src);
        }
    };

    load_b(0); CP_COMMIT();
    load_b(1); CP_COMMIT();
    load_b(2); CP_COMMIT();

    // ---- epilogue vectors ----
    for (int i = tx; i < Hh; i += 256) {
        su[i] = g_u[b * Hh + i]; sw3[i] = g_w3c[i]; sv[i] = v[i];
    }

    // ---- A tile: enc rows t0..t0+127 of batch b, fp32 -> fp16 swizzled smem ----
    {
        const int rs = tx >> 4, kg = tx & 15;
        #pragma unroll
        for (int rr = 0; rr < 8; rr++) {
            const int r = rr * 16 + rs;
            const float* rowp = enc + ((size_t)(t0 + r) * Bb + b) * Hh;
            #pragma unroll
            for (int kk = 0; kk < 8; kk++) {
                const int k0 = kk * 64 + kg * 4;
                float4 e = *(const float4*)(rowp + k0);
                __half2 p0 = __floats2half2_rn(e.x, e.y);
                __half2 p1 = __floats2half2_rn(e.z, e.w);
                uint2 uu;
                uu.x = *reinterpret_cast<unsigned*>(&p0);
                uu.y = *reinterpret_cast<unsigned*>(&p1);
                *(uint2*)(smem + OFF_A + kk * 16384 +
                          swz((unsigned)(r * 128 + (k0 & 63) * 2))) = uu;
            }
        }
    }

    // ---- per-lane ldmatrix address precompute ----
    unsigned aBase[2], aXor[2];
    {
        const int rA = mw * 32 + ((l >> 3) & 1) * 8 + (l & 7);
        #pragma unroll
        for (int mi = 0; mi < 2; mi++) {
            const int row = rA + mi * 16;
            aBase[mi] = sb + OFF_A + (unsigned)(row * 128);
            aXor[mi]  = (unsigned)((row & 7) << 4);
        }
    }
    const int cbA = ((l >> 4) & 1) * 8;
    unsigned bBase[2], bXor[2];
    {
        const int rB = nw * 32 + ((l >> 4) & 1) * 8 + (l & 7);
        #pragma unroll
        for (int nj = 0; nj < 2; nj++) {
            const int row = rB + nj * 16;
            bBase[nj] = sb + OFF_B + (unsigned)(row * 128);
            bXor[nj]  = (unsigned)((row & 7) << 4);
        }
    }
    const int cbB = ((l >> 3) & 1) * 8;

    float cov[4];
    #pragma unroll
    for (int mi = 0; mi < 2; mi++)
        #pragma unroll
        for (int half = 0; half < 2; half++)
            cov[mi * 2 + half] =
                coverage[b * Tt + t0 + mw * 32 + mi * 16 + (l >> 2) + half * 8];

    float acc[2][4][4];
    float sc[4] = {0.f, 0.f, 0.f, 0.f};
    const int c0 = (l & 3) * 2;

    // ---- main pipeline: 32 chunks (128k each), 3-deep cp.async, 1 sync/iter ----
    for (int i = 0; i < 32; i++) {
        CP_WAIT2();
        __syncthreads();
        if (i + 3 < 32) load_b(i + 3);
        CP_COMMIT();

        const int kc2 = i & 3, ht = i >> 2;
        if (kc2 == 0) {
            #pragma unroll
            for (int mi = 0; mi < 2; mi++)
                #pragma unroll
                for (int ni = 0; ni < 4; ni++)
                    #pragma unroll
                    for (int q = 0; q < 4; q++) acc[mi][ni][q] = 0.f;
        }

        const unsigned bB = (unsigned)(i & 3) * 16384;
        #pragma unroll
        for (int s = 0; s < 8; s++) {
            const unsigned aOff = (unsigned)((kc2 * 2 + (s >> 2)) * 16384);
            const unsigned bOff = bB + (unsigned)((s >> 2) * 8192);
            const unsigned colA = (unsigned)((((s & 3) * 16) + cbA) * 2);
            const unsigned colB = (unsigned)((((s & 3) * 16) + cbB) * 2);
            unsigned av[2][4], bv[2][4];
            LDSM_X4(av[0], aBase[0] + aOff + (colA ^ aXor[0]));
            LDSM_X4(av[1], aBase[1] + aOff + (colA ^ aXor[1]));
            LDSM_X4(bv[0], bBase[0] + bOff + (colB ^ bXor[0]));
            LDSM_X4(bv[1], bBase[1] + bOff + (colB ^ bXor[1]));
            #pragma unroll
            for (int mi = 0; mi < 2; mi++) {
                MMA_F16(acc[mi][0], av[mi], bv[0][0], bv[0][1]);
                MMA_F16(acc[mi][1], av[mi], bv[0][2], bv[0][3]);
                MMA_F16(acc[mi][2], av[mi], bv[1][0], bv[1][1]);
                MMA_F16(acc[mi][3], av[mi], bv[1][2], bv[1][3]);
            }
        }

        if (kc2 == 3) {
            // epilogue for h-tile ht: energy + u + cov*w3c -> relu -> dot v
            #pragma unroll
            for (int ni = 0; ni < 4; ni++) {
                const int h = ht * 64 + nw * 32 + ni * 8 + c0;
                const float2 u2 = *(const float2*)&su[h];
                const float2 w2 = *(const float2*)&sw3[h];
                const float2 v2 = *(const float2*)&sv[h];
                #pragma unroll
                for (int mi = 0; mi < 2; mi++) {
                    float e0 = acc[mi][ni][0] + u2.x + cov[mi * 2] * w2.x;
                    float e1 = acc[mi][ni][1] + u2.y + cov[mi * 2] * w2.y;
                    sc[mi * 2] += v2.x * fmaxf(e0, 0.f) + v2.y * fmaxf(e1, 0.f);
                    float e2 = acc[mi][ni][2] + u2.x + cov[mi * 2 + 1] * w2.x;
                    float e3 = acc[mi][ni][3] + u2.y + cov[mi * 2 + 1] * w2.y;
                    sc[mi * 2 + 1] += v2.x * fmaxf(e2, 0.f) + v2.y * fmaxf(e3, 0.f);
                }
            }
        }
    }

    // ---- reduce: sum over the 4 lanes sharing a row, then over the 2 n-warps ----
    #pragma unroll
    for (int q = 1; q < 4; q <<= 1)
        #pragma unroll
        for (int j = 0; j < 4; j++)
            sc[j] += __shfl_xor_sync(0xFFFFFFFFu, sc[j], q);

    float* sred = (float*)(smem + OFF_SRED);
    __syncthreads();
    if ((l & 3) == 0) {
        #pragma unroll
        for (int mi = 0; mi < 2; mi++)
            #pragma unroll
            for (int half = 0; half < 2; half++)
                sred[nw * 128 + mw * 32 + mi * 16 + (l >> 2) + half * 8] = sc[mi * 2 + half];
    }
    __syncthreads();
    if (tx < 128) g_scores[b * Tt + t0 + tx] = sred[tx] + sred[128 + tx];
}

// ---------------- kernel 3: softmax over T + coverage update ----------------
__global__ __launch_bounds__(512) void softmax_kernel(
    const float* __restrict__ coverage, float* __restrict__ out, int write_cov)
{
    __shared__ float red[16];
    const int b = blockIdx.x, tx = threadIdx.x;
    const int wi = tx >> 5, li = tx & 31;
    const float* s = g_scores + b * Tt;

    float4 x = ((const float4*)s)[tx];    // elements 4tx..4tx+3

    float m = fmaxf(fmaxf(x.x, x.y), fmaxf(x.z, x.w));
    #pragma unroll
    for (int q = 16; q > 0; q >>= 1) m = fmaxf(m, __shfl_xor_sync(0xFFFFFFFFu, m, q));
    if (li == 0) red[wi] = m;
    __syncthreads();
    if (tx < 32) {
        float mm = (tx < 16) ? red[tx] : -3.0e38f;
        #pragma unroll
        for (int q = 8; q > 0; q >>= 1) mm = fmaxf(mm, __shfl_xor_sync(0xFFFFFFFFu, mm, q));
        if (tx == 0) red[0] = mm;
    }
    __syncthreads();
    m = red[0];

    float4 e;
    e.x = __expf(x.x - m); e.y = __expf(x.y - m);
    e.z = __expf(x.z - m); e.w = __expf(x.w - m);
    float sum = (e.x + e.y) + (e.z + e.w);
    #pragma unroll
    for (int q = 16; q > 0; q >>= 1) sum += __shfl_xor_sync(0xFFFFFFFFu, sum, q);
    __syncthreads();
    if (li == 0) red[wi] = sum;
    __syncthreads();
    if (tx < 32) {
        float ss = (tx < 16) ? red[tx] : 0.f;
        #pragma unroll
        for (int q = 8; q > 0; q >>= 1) ss += __shfl_xor_sync(0xFFFFFFFFu, ss, q);
        if (tx == 0) red[0] = ss;
    }
    __syncthreads();
    const float inv = 1.f / red[0];

    float4 w;
    w.x = e.x * inv; w.y = e.y * inv; w.z = e.z * inv; w.w = e.w * inv;
    ((float4*)(out + b * Tt))[tx] = w;
    if (write_cov) {
        float4 c = ((const float4*)(coverage + b * Tt))[tx];
        c.x += w.x; c.y += w.y; c.z += w.z; c.w += w.w;
        ((float4*)(out + Bb * Tt + b * Tt))[tx] = c;
    }
}

// ---------------- launch ----------------
extern "C" void kernel_launch(void* const* d_in, const int* in_sizes, int n_in,
                              void* d_out, int out_size) {
    const float* hidden   = (const float*)d_in[0];
    const float* enc      = (const float*)d_in[1];
    const float* coverage = (const float*)d_in[2];
    const float* W_attn   = (const float*)d_in[3];
    const float* b_attn   = (const float*)d_in[4];
    const float* v        = (const float*)d_in[5];
    const float* W_cov    = (const float*)d_in[6];
    float* out = (float*)d_out;

    cudaFuncSetAttribute(gemm_scores_kernel,
                         cudaFuncAttributeMaxDynamicSharedMemorySize, GEMM_SMEM);

    w2_convert_kernel<<<256, 256>>>(W_attn);
    precompute_kernel<<<dim3(Bb + 1, 8), 512>>>(hidden, W_attn, b_attn, W_cov);
    gemm_scores_kernel<<<dim3(Tt / 128, Bb), 256, GEMM_SMEM>>>(enc, coverage, v);

    const int write_cov = (out_size >= 2 * Bb * Tt) ? 1 : 0;
    softmax_kernel<<<Bb, 512>>>(coverage, out, write_cov);
}